// round 12
// baseline (speedup 1.0000x reference)
#include <cuda_runtime.h>
#include <math.h>

// FixedRadiusNeighborQuery — single persistent kernel:
//   count -> [grid barrier] -> scan -> [barrier] -> scatter -> [barrier] -> query
//
// Grid = 148 blocks x 1024 threads: one block per SM, all co-resident
// (1 block/SM occupancy), so the monotonic-counter grid barrier cannot
// deadlock. Barrier targets are successive multiples of 148, so the counter
// never needs resetting and is safe across graph replays.
//
// Structure: 2-D 64x64 (x,y) binning over [-6.5,6.5]^2; query scans bins
// intersecting [q-0.302, q+0.302]^2 — a provable superset of the reference
// accept set (bin fn monotone; 0.302 >> max accepted |dx| = 0.30017 incl.
// the d2 chain's fp error). Hits ballot-compacted to per-warp smem as
// (d2bits, idx) keys; bitonic-32 sort (cnt<=32) or dual sort-32 + merge
// (cnt<=64) -> exact (d2 asc, idx asc) top-32. cnt>64 -> noinline fallback.
//
// Numerics identical to the JAX reference:
//   p2 = (x*x + y*y) + z*z ;  dot = fma(qz,pz, fma(qy,py, qx*px))
//   d2 = fma(dot,-2, q2+p2) ; valid = d2 <= 0.09f
//   dist = sqrtf(max(max(d2,0),1e-12))

#define FRNQ_LIMIT 32
#define NX 64
#define NBINS2 (NX * NX)
#define MAXN  65536
#define MAXB  16
#define XMIN  (-6.5f)
#define INVW  (NX / 13.0f)
#define RWIN  0.302f

#define GRID 148
#define TPB  1024
#define WPB  (TPB / 32)
#define PREP_V (NBINS2 / TPB)       // 4 bins per thread in the scan
#define CAP 64
#define PADKEY 0xFFFFFFFFFFFFFFFFull

typedef unsigned long long u64;
typedef unsigned int u32;

__device__ float4   g_pts4[MAXN];
__device__ int      g_pidx[MAXN];
__device__ int      g_start[MAXB * (NBINS2 + 1)];
__device__ int      g_hist[MAXB * NBINS2];   // zero-init; scan re-zeroes it
__device__ int      g_cur[MAXB * NBINS2];
__device__ unsigned g_arrive;                // monotonic barrier counter

__device__ __forceinline__ int bin1(float v) {
    int b = (int)floorf((v - XMIN) * INVW);
    return min(max(b, 0), NX - 1);
}

// Grid barrier: all GRID blocks arrive; targets are multiples of GRID on a
// monotonic counter (no reset needed; replay-safe; wraps after ~29M barriers).
__device__ __forceinline__ void grid_barrier() {
    __threadfence();
    __syncthreads();
    if (threadIdx.x == 0) {
        unsigned old;
        asm volatile("atom.add.release.gpu.global.u32 %0, [%1], %2;"
                     : "=r"(old) : "l"(&g_arrive), "r"(1u) : "memory");
        unsigned my     = old + 1u;
        unsigned target = ((my + GRID - 1u) / GRID) * GRID;
        unsigned cur;
        do {
            asm volatile("ld.acquire.gpu.global.u32 %0, [%1];"
                         : "=r"(cur) : "l"(&g_arrive) : "memory");
        } while (cur < target);
    }
    __syncthreads();
}

__device__ __forceinline__ u64 shflx64(u64 v, int j) {
    return __shfl_xor_sync(0xffffffffu, v, j);
}
__device__ __forceinline__ void cswap(u64& v, int j, bool takeMin) {
    u64 o  = shflx64(v, j);
    u64 mn = (v < o) ? v : o;
    u64 mx = (v < o) ? o : v;
    v = takeMin ? mn : mx;
}
__device__ __forceinline__ void sort32(u64& v, int lane) {
    #pragma unroll
    for (int k = 2; k <= 32; k <<= 1) {
        #pragma unroll
        for (int j = k >> 1; j > 0; j >>= 1) {
            bool up    = ((lane & k) == 0) || (k == 32);
            bool lower = ((lane & j) == 0);
            cswap(v, j, up == lower);
        }
    }
}
__device__ __forceinline__ void sort32x2(u64& a, u64& b, int lane) {
    #pragma unroll
    for (int k = 2; k <= 32; k <<= 1) {
        #pragma unroll
        for (int j = k >> 1; j > 0; j >>= 1) {
            bool up    = ((lane & k) == 0) || (k == 32);
            bool lower = ((lane & j) == 0);
            bool tm    = (up == lower);
            cswap(a, j, tm);
            cswap(b, j, tm);
        }
    }
}

// Fallback: per-lane insert lists + reduce-merge (proven path). Rare.
__device__ __noinline__
void frnq_fallback(int q, int lane, float qx, float qy, float qz, float q2,
                   const int* st, int bxlo, int bxhi, int bylo, int byhi,
                   float* out_idx, float* out_dist)
{
    const float R2  = 0.09f;
    const float INF = __int_as_float(0x7f800000);
    float ld[FRNQ_LIMIT];
    int   li[FRNQ_LIMIT];
    int   n = 0;

    for (int by = bylo; by <= byhi; ++by) {
        const int beg = st[by * NX + bxlo];
        const int end = st[by * NX + bxhi + 1];
        for (int k = beg + lane; k < end; k += 32) {
            float4 p  = g_pts4[k];
            float dot = __fmaf_rn(qz, p.z, __fmaf_rn(qy, p.y, __fmul_rn(qx, p.x)));
            float d2  = __fmaf_rn(dot, -2.0f, __fadd_rn(q2, p.w));
            if (d2 <= R2) {
                d2 = fmaxf(d2, 0.0f);
                int idx = g_pidx[k];
                if (n < FRNQ_LIMIT || d2 < ld[FRNQ_LIMIT - 1]) {
                    int j = (n < FRNQ_LIMIT) ? n : (FRNQ_LIMIT - 1);
                    while (j > 0 && ld[j - 1] > d2) {
                        ld[j] = ld[j - 1]; li[j] = li[j - 1]; --j;
                    }
                    ld[j] = d2; li[j] = idx;
                    if (n < FRNQ_LIMIT) ++n;
                }
            }
        }
    }

    int   pos = 0;
    float hd  = (n > 0) ? ld[0] : INF;
    int   hi2 = (n > 0) ? li[0] : 0x7fffffff;
    float rd  = INF;
    int   ri  = -1;
    for (int r = 0; r < FRNQ_LIMIT; ++r) {
        float bd = hd;
        #pragma unroll
        for (int off = 16; off > 0; off >>= 1)
            bd = fminf(bd, __shfl_xor_sync(0xffffffffu, bd, off));
        if (bd == INF) break;
        unsigned m  = __ballot_sync(0xffffffffu, hd == bd);
        int      wl = __ffs(m) - 1;
        if (__popc(m) > 1) {
            int myi = (hd == bd) ? hi2 : 0x7fffffff;
            int mi  = myi;
            #pragma unroll
            for (int off = 16; off > 0; off >>= 1)
                mi = min(mi, __shfl_xor_sync(0xffffffffu, mi, off));
            m  = __ballot_sync(0xffffffffu, myi == mi);
            wl = __ffs(m) - 1;
        }
        int wi = __shfl_sync(0xffffffffu, hi2, wl);
        if (r == lane) { rd = bd; ri = wi; }
        if (lane == wl) {
            ++pos;
            if (pos < n) { hd = ld[pos]; hi2 = li[pos]; }
            else         { hd = INF;     hi2 = 0x7fffffff; }
        }
    }
    const size_t o   = (size_t)q * FRNQ_LIMIT + lane;
    const bool   val = (rd < 1e29f);
    out_idx[o]  = val ? (float)ri : -1.0f;
    out_dist[o] = val ? sqrtf(fmaxf(rd, 1e-12f)) : 0.0f;
}

__global__ __launch_bounds__(TPB, 1)
void frnq_all_kernel(const float* __restrict__ points,
                     const int*   __restrict__ row_splits, int B,
                     const float* __restrict__ qpts,
                     const int*   __restrict__ q_splits,   int n_qs,
                     int Q,
                     float* __restrict__ out_idx,
                     float* __restrict__ out_dist)
{
    __shared__ u64 buf[WPB][CAP];        // 16 KB, query phase
    __shared__ int s_ps[MAXB + 1];
    __shared__ int s_qs[MAXB + 1];
    __shared__ int wsum[WPB];

    const int tid  = threadIdx.x;
    const int lane = tid & 31;
    const int warp = tid >> 5;

    if (tid <= B) s_ps[tid] = row_splits[tid];
    if (tid >= 64 && tid - 64 < n_qs) s_qs[tid - 64] = q_splits[tid - 64];
    __syncthreads();
    const int N = s_ps[B];

    // ---- Phase A: count (grid-stride, 148 SMs) ----
    for (int i = blockIdx.x * TPB + tid; i < N; i += GRID * TPB) {
        int b = 0;
        for (int j = 1; j < B; ++j)
            if (i >= s_ps[j]) b = j;
        int bx = bin1(points[3 * i + 0]);
        int by = bin1(points[3 * i + 1]);
        atomicAdd(&g_hist[b * NBINS2 + by * NX + bx], 1);
    }
    grid_barrier();

    // ---- Phase B: per-batch exclusive scan (blocks 0..B-1) ----
    if (blockIdx.x < B) {
        const int b    = blockIdx.x;
        const int ps   = s_ps[b];
        const int base = tid * PREP_V;
        int loc[PREP_V];
        int s = 0;
        #pragma unroll
        for (int v = 0; v < PREP_V; ++v) {
            loc[v] = s;
            s += g_hist[b * NBINS2 + base + v];
            g_hist[b * NBINS2 + base + v] = 0;   // leave zeroed for next call
        }
        int inc = s;
        #pragma unroll
        for (int o = 1; o < 32; o <<= 1) {
            int t = __shfl_up_sync(0xffffffffu, inc, o);
            if (lane >= o) inc += t;
        }
        if (lane == 31) wsum[warp] = inc;
        __syncthreads();
        if (warp == 0) {
            int w  = wsum[lane];
            int wi = w;
            #pragma unroll
            for (int o = 1; o < 32; o <<= 1) {
                int t = __shfl_up_sync(0xffffffffu, wi, o);
                if (lane >= o) wi += t;
            }
            wsum[lane] = wi - w;   // exclusive warp offsets
        }
        __syncthreads();
        const int excl = inc - s + wsum[warp];
        const int gb   = b * (NBINS2 + 1);
        #pragma unroll
        for (int v = 0; v < PREP_V; ++v) {
            int pos = ps + excl + loc[v];
            g_start[gb + base + v]      = pos;
            g_cur[b * NBINS2 + base + v] = pos;
        }
        if (tid == 0) g_start[gb + NBINS2] = s_ps[b + 1];
    }
    grid_barrier();

    // ---- Phase C: scatter (grid-stride, 148 SMs) ----
    for (int i = blockIdx.x * TPB + tid; i < N; i += GRID * TPB) {
        int b = 0;
        for (int j = 1; j < B; ++j)
            if (i >= s_ps[j]) b = j;
        float x = points[3 * i + 0];
        float y = points[3 * i + 1];
        float z = points[3 * i + 2];
        float p2 = __fadd_rn(__fadd_rn(__fmul_rn(x, x), __fmul_rn(y, y)),
                             __fmul_rn(z, z));
        int bn  = bin1(y) * NX + bin1(x);
        int pos = atomicAdd(&g_cur[b * NBINS2 + bn], 1);
        g_pts4[pos] = make_float4(x, y, z, p2);
        g_pidx[pos] = i;
    }
    grid_barrier();

    // ---- Phase D: query (1 warp per query, grid-stride over queries) ----
    const float R2 = 0.09f;
    for (int q = blockIdx.x * WPB + warp; q < Q; q += GRID * WPB) {
        int qb = 0;
        for (int i = 1; i < n_qs; ++i)
            if (s_qs[i] <= q) qb = i;

        const float qx = qpts[3 * q + 0];
        const float qy = qpts[3 * q + 1];
        const float qz = qpts[3 * q + 2];
        const float q2 = __fadd_rn(__fadd_rn(__fmul_rn(qx, qx), __fmul_rn(qy, qy)),
                                   __fmul_rn(qz, qz));

        const int bxlo  = bin1(qx - RWIN);
        const int bxhi  = bin1(qx + RWIN);
        const int bylo  = bin1(qy - RWIN);
        const int byhi  = bin1(qy + RWIN);
        const int nrows = byhi - bylo + 1;
        const int* st   = g_start + qb * (NBINS2 + 1);

        // one parallel LDG round for all row ranges, shfl-broadcast later
        int sv = 0;
        if (lane < 2 * nrows)
            sv = st[(bylo + (lane >> 1)) * NX + ((lane & 1) ? (bxhi + 1) : bxlo)];

        int cnt = 0;
        for (int r = 0; r < nrows; ++r) {
            const int beg = __shfl_sync(0xffffffffu, sv, 2 * r);
            const int end = __shfl_sync(0xffffffffu, sv, 2 * r + 1);
            for (int k0 = beg; k0 < end; k0 += 32) {
                const int  k   = k0 + lane;
                const bool act = (k < end);
                float4 p = make_float4(0.f, 0.f, 0.f, 1e30f);
                if (act) p = g_pts4[k];
                float dot = __fmaf_rn(qz, p.z, __fmaf_rn(qy, p.y, __fmul_rn(qx, p.x)));
                float d2  = __fmaf_rn(dot, -2.0f, __fadd_rn(q2, p.w));
                bool hit  = act && (d2 <= R2);
                unsigned m = __ballot_sync(0xffffffffu, hit);
                if (hit) {
                    int off = cnt + __popc(m & ((1u << lane) - 1u));
                    if (off < CAP) {
                        float d2c = fmaxf(d2, 0.0f);
                        buf[warp][off] = ((u64)__float_as_uint(d2c) << 32) |
                                         (u32)g_pidx[k];
                    }
                }
                cnt += __popc(m);
            }
        }

        const size_t o = (size_t)q * FRNQ_LIMIT + lane;

        if (cnt == 0) {              // warp-uniform: skip the sort entirely
            out_idx[o]  = -1.0f;
            out_dist[o] = 0.0f;
            continue;
        }
        if (cnt > CAP) {             // practically never; correctness anyway
            frnq_fallback(q, lane, qx, qy, qz, q2, st,
                          bxlo, bxhi, bylo, byhi, out_idx, out_dist);
            continue;
        }

        __syncwarp();
        u64 v0 = (lane < cnt) ? buf[warp][lane] : PADKEY;

        if (cnt <= 32) {
            sort32(v0, lane);                       // 15 rounds
        } else {
            u64 v1 = (lane + 32 < cnt) ? buf[warp][lane + 32] : PADKEY;
            sort32x2(v0, v1, lane);                 // 15 rounds, 2-way ILP
            u64 w = shflx64(v1, 31);                // reverse of v1
            v0 = (v0 < w) ? v0 : w;                 // bitonic sequence of mins
            #pragma unroll
            for (int j = 16; j > 0; j >>= 1)        // 5-round bitonic merge
                cswap(v0, j, (lane & j) == 0);
        }

        const bool  val = (v0 != PADKEY);
        const float rd  = __uint_as_float((u32)(v0 >> 32));
        const int   ri  = (int)(u32)v0;
        out_idx[o]  = val ? (float)ri : -1.0f;
        out_dist[o] = val ? sqrtf(fmaxf(rd, 1e-12f)) : 0.0f;
    }
}

// ---------------------------------------------------------------------------
extern "C" void kernel_launch(void* const* d_in, const int* in_sizes, int n_in,
                              void* d_out, int out_size)
{
    const float* points     = (const float*)d_in[0];
    const int*   row_splits = (const int*)  d_in[1];
    const float* qpts       = (const float*)d_in[2];
    const int*   q_splits   = (const int*)  d_in[3];

    const int n_qs = in_sizes[3];
    const int B    = in_sizes[1] - 1;
    const int Q    = in_sizes[2] / 3;

    float* out_idx  = (float*)d_out;
    float* out_dist = out_idx + (size_t)Q * FRNQ_LIMIT;

    frnq_all_kernel<<<GRID, TPB>>>(points, row_splits, B,
                                   qpts, q_splits, n_qs,
                                   Q, out_idx, out_dist);
}

// round 13
// speedup vs baseline: 1.2685x; 1.2685x over previous
#include <cuda_runtime.h>
#include <math.h>

// FixedRadiusNeighborQuery — 2-D binned pruning + smem-atomic compaction.
//
// Pipeline (2 graph-captured launches):
//   K1 prep (one block per batch, 1024 thr): smem 64x64 histogram ->
//      in-place block exclusive scan -> g_start; smem-cursor scatter of
//      bin-sorted float4{x,y,z,p2} + orig idx into global scratch.
//   K2 query: 1 warp/query; scan bins intersecting [q-0.302,q+0.302]^2
//      (provable superset of the reference accept set: bin fn monotone,
//       0.302 >> max accepted |dx| = 0.30017 incl. d2-chain fp error).
//      Hits compacted via per-warp smem atomicAdd (hit-path only: the scan
//      loop has NO per-iteration warp sync, so chunk loads overlap).
//      Keys (d2bits,idx) bitonic-sorted -> exact (d2 asc, idx asc) top-32.
//      cnt>64 (practically never) -> noinline fallback rescan.
//
// Numerics identical to the JAX reference:
//   p2 = (x*x + y*y) + z*z ;  dot = fma(qz,pz, fma(qy,py, qx*px))
//   d2 = fma(dot,-2, q2+p2) ; valid = d2 <= 0.09f
//   dist = sqrtf(max(max(d2,0),1e-12))

#define FRNQ_LIMIT 32
#define NX 64
#define NBINS2 (NX * NX)
#define MAXN  65536
#define MAXB  16
#define XMIN  (-6.5f)
#define INVW  (NX / 13.0f)
#define RWIN  0.302f

typedef unsigned long long u64;
typedef unsigned int u32;

__device__ float4 g_pts4[MAXN];
__device__ int    g_pidx[MAXN];
__device__ int    g_start[MAXB * (NBINS2 + 1)];

__device__ __forceinline__ int bin1(float v) {
    int b = (int)floorf((v - XMIN) * INVW);
    return min(max(b, 0), NX - 1);
}

// ---------------- K1: fused count + scan + scatter (1 block per batch) -----
#define PREP_T 1024
#define PREP_V (NBINS2 / PREP_T)   // 4 bins per thread

__global__ __launch_bounds__(PREP_T)
void frnq_prep_kernel(const float* __restrict__ points,
                      const int*   __restrict__ row_splits)
{
    __shared__ int hist[NBINS2];          // hist -> absolute cursor, in place
    __shared__ int wsum[PREP_T / 32];

    const int b    = blockIdx.x;
    const int ps   = row_splits[b];
    const int pe   = row_splits[b + 1];
    const int tid  = threadIdx.x;
    const int lane = tid & 31;
    const int wid  = tid >> 5;
    const int base = tid * PREP_V;

    #pragma unroll
    for (int v = 0; v < PREP_V; ++v) hist[base + v] = 0;
    __syncthreads();

    for (int i = ps + tid; i < pe; i += PREP_T) {
        int bx = bin1(points[3 * i + 0]);
        int by = bin1(points[3 * i + 1]);
        atomicAdd(&hist[by * NX + bx], 1);
    }
    __syncthreads();

    int loc[PREP_V];
    int s = 0;
    #pragma unroll
    for (int v = 0; v < PREP_V; ++v) { loc[v] = s; s += hist[base + v]; }

    int inc = s;
    #pragma unroll
    for (int o = 1; o < 32; o <<= 1) {
        int t = __shfl_up_sync(0xffffffffu, inc, o);
        if (lane >= o) inc += t;
    }
    if (lane == 31) wsum[wid] = inc;
    __syncthreads();
    if (wid == 0) {
        int w  = wsum[lane];
        int wi = w;
        #pragma unroll
        for (int o = 1; o < 32; o <<= 1) {
            int t = __shfl_up_sync(0xffffffffu, wi, o);
            if (lane >= o) wi += t;
        }
        wsum[lane] = wi - w;
    }
    __syncthreads();
    const int excl = inc - s + wsum[wid];

    const int gb = b * (NBINS2 + 1);
    #pragma unroll
    for (int v = 0; v < PREP_V; ++v) {
        int pos = ps + excl + loc[v];
        g_start[gb + base + v] = pos;
        hist[base + v] = pos;
    }
    if (tid == 0) g_start[gb + NBINS2] = pe;
    __syncthreads();

    for (int i = ps + tid; i < pe; i += PREP_T) {
        float x = points[3 * i + 0];
        float y = points[3 * i + 1];
        float z = points[3 * i + 2];
        float p2 = __fadd_rn(__fadd_rn(__fmul_rn(x, x), __fmul_rn(y, y)),
                             __fmul_rn(z, z));
        int bn  = bin1(y) * NX + bin1(x);
        int pos = atomicAdd(&hist[bn], 1);
        g_pts4[pos] = make_float4(x, y, z, p2);
        g_pidx[pos] = i;
    }
}

// ---------------- K2: query ----------------
#define FRNQ_QWARPS 8
#define FRNQ_QTHREADS (FRNQ_QWARPS * 32)
#define CAP 64
#define PADKEY 0xFFFFFFFFFFFFFFFFull

__device__ __forceinline__ u64 shflx64(u64 v, int j) {
    return __shfl_xor_sync(0xffffffffu, v, j);
}
__device__ __forceinline__ void cswap(u64& v, int j, bool takeMin) {
    u64 o  = shflx64(v, j);
    u64 mn = (v < o) ? v : o;
    u64 mx = (v < o) ? o : v;
    v = takeMin ? mn : mx;
}
__device__ __forceinline__ void sort32(u64& v, int lane) {
    #pragma unroll
    for (int k = 2; k <= 32; k <<= 1) {
        #pragma unroll
        for (int j = k >> 1; j > 0; j >>= 1) {
            bool up    = ((lane & k) == 0) || (k == 32);
            bool lower = ((lane & j) == 0);
            cswap(v, j, up == lower);
        }
    }
}
__device__ __forceinline__ void sort32x2(u64& a, u64& b, int lane) {
    #pragma unroll
    for (int k = 2; k <= 32; k <<= 1) {
        #pragma unroll
        for (int j = k >> 1; j > 0; j >>= 1) {
            bool up    = ((lane & k) == 0) || (k == 32);
            bool lower = ((lane & j) == 0);
            bool tm    = (up == lower);
            cswap(a, j, tm);
            cswap(b, j, tm);
        }
    }
}

// Fallback: per-lane insert lists + reduce-merge (proven R8 path). Rare.
__device__ __noinline__
void frnq_fallback(int q, int lane, float qx, float qy, float qz, float q2,
                   const int* st, int bxlo, int bxhi, int bylo, int byhi,
                   float* out_idx, float* out_dist)
{
    const float R2  = 0.09f;
    const float INF = __int_as_float(0x7f800000);
    float ld[FRNQ_LIMIT];
    int   li[FRNQ_LIMIT];
    int   n = 0;

    for (int by = bylo; by <= byhi; ++by) {
        const int beg = st[by * NX + bxlo];
        const int end = st[by * NX + bxhi + 1];
        for (int k = beg + lane; k < end; k += 32) {
            float4 p  = g_pts4[k];
            float dot = __fmaf_rn(qz, p.z, __fmaf_rn(qy, p.y, __fmul_rn(qx, p.x)));
            float d2  = __fmaf_rn(dot, -2.0f, __fadd_rn(q2, p.w));
            if (d2 <= R2) {
                d2 = fmaxf(d2, 0.0f);
                int idx = g_pidx[k];
                if (n < FRNQ_LIMIT || d2 < ld[FRNQ_LIMIT - 1]) {
                    int j = (n < FRNQ_LIMIT) ? n : (FRNQ_LIMIT - 1);
                    while (j > 0 && ld[j - 1] > d2) {
                        ld[j] = ld[j - 1]; li[j] = li[j - 1]; --j;
                    }
                    ld[j] = d2; li[j] = idx;
                    if (n < FRNQ_LIMIT) ++n;
                }
            }
        }
    }

    int   pos = 0;
    float hd  = (n > 0) ? ld[0] : INF;
    int   hi2 = (n > 0) ? li[0] : 0x7fffffff;
    float rd  = INF;
    int   ri  = -1;
    for (int r = 0; r < FRNQ_LIMIT; ++r) {
        float bd = hd;
        #pragma unroll
        for (int off = 16; off > 0; off >>= 1)
            bd = fminf(bd, __shfl_xor_sync(0xffffffffu, bd, off));
        if (bd == INF) break;
        unsigned m  = __ballot_sync(0xffffffffu, hd == bd);
        int      wl = __ffs(m) - 1;
        if (__popc(m) > 1) {
            int myi = (hd == bd) ? hi2 : 0x7fffffff;
            int mi  = myi;
            #pragma unroll
            for (int off = 16; off > 0; off >>= 1)
                mi = min(mi, __shfl_xor_sync(0xffffffffu, mi, off));
            m  = __ballot_sync(0xffffffffu, myi == mi);
            wl = __ffs(m) - 1;
        }
        int wi = __shfl_sync(0xffffffffu, hi2, wl);
        if (r == lane) { rd = bd; ri = wi; }
        if (lane == wl) {
            ++pos;
            if (pos < n) { hd = ld[pos]; hi2 = li[pos]; }
            else         { hd = INF;     hi2 = 0x7fffffff; }
        }
    }
    const size_t o   = (size_t)q * FRNQ_LIMIT + lane;
    const bool   val = (rd < 1e29f);
    out_idx[o]  = val ? (float)ri : -1.0f;
    out_dist[o] = val ? sqrtf(fmaxf(rd, 1e-12f)) : 0.0f;
}

__global__ __launch_bounds__(FRNQ_QTHREADS)
void frnq_query_kernel(const float* __restrict__ qpts,
                       const int*   __restrict__ q_splits, int n_qs,
                       int Q,
                       float* __restrict__ out_idx,
                       float* __restrict__ out_dist)
{
    __shared__ u64 buf[FRNQ_QWARPS][CAP];
    __shared__ int wcnt[FRNQ_QWARPS];

    const int lane = threadIdx.x & 31;
    const int warp = threadIdx.x >> 5;
    const int q    = blockIdx.x * FRNQ_QWARPS + warp;
    if (q >= Q) return;

    const float R2 = 0.09f;

    if (lane == 0) wcnt[warp] = 0;

    int qb = 0;
    for (int i = 1; i < n_qs; ++i)
        if (q_splits[i] <= q) qb = i;

    const float qx = qpts[3 * q + 0];
    const float qy = qpts[3 * q + 1];
    const float qz = qpts[3 * q + 2];
    const float q2 = __fadd_rn(__fadd_rn(__fmul_rn(qx, qx), __fmul_rn(qy, qy)),
                               __fmul_rn(qz, qz));

    const int bxlo  = bin1(qx - RWIN);
    const int bxhi  = bin1(qx + RWIN);
    const int bylo  = bin1(qy - RWIN);
    const int byhi  = bin1(qy + RWIN);
    const int nrows = byhi - bylo + 1;
    const int* st   = g_start + qb * (NBINS2 + 1);

    // one parallel LDG round for all row ranges, shfl-broadcast later
    int sv = 0;
    if (lane < 2 * nrows)
        sv = st[(bylo + (lane >> 1)) * NX + ((lane & 1) ? (bxhi + 1) : bxlo)];
    __syncwarp();   // wcnt init + sv ready

    // scan loop: NO per-iteration warp sync — hit path takes a smem atomic.
    for (int r = 0; r < nrows; ++r) {
        const int beg = __shfl_sync(0xffffffffu, sv, 2 * r);
        const int end = __shfl_sync(0xffffffffu, sv, 2 * r + 1);
        for (int k = beg + lane; k < end; k += 32) {
            float4 p  = g_pts4[k];
            float dot = __fmaf_rn(qz, p.z, __fmaf_rn(qy, p.y, __fmul_rn(qx, p.x)));
            float d2  = __fmaf_rn(dot, -2.0f, __fadd_rn(q2, p.w));
            if (d2 <= R2) {                        // rare (~5% of evals)
                int off = atomicAdd(&wcnt[warp], 1);
                if (off < CAP) {
                    float d2c = fmaxf(d2, 0.0f);
                    buf[warp][off] = ((u64)__float_as_uint(d2c) << 32) |
                                     (u32)g_pidx[k];
                }
            }
        }
    }
    __syncwarp();
    const int cnt = wcnt[warp];

    const size_t o = (size_t)q * FRNQ_LIMIT + lane;

    if (cnt == 0) {                 // warp-uniform: skip the sort entirely
        out_idx[o]  = -1.0f;
        out_dist[o] = 0.0f;
        return;
    }
    if (cnt > CAP) {                // practically never; correctness anyway
        frnq_fallback(q, lane, qx, qy, qz, q2, st,
                      bxlo, bxhi, bylo, byhi, out_idx, out_dist);
        return;
    }

    u64 v0 = (lane < cnt) ? buf[warp][lane] : PADKEY;

    if (cnt <= 32) {
        sort32(v0, lane);                         // 15 rounds
    } else {
        u64 v1 = (lane + 32 < cnt) ? buf[warp][lane + 32] : PADKEY;
        sort32x2(v0, v1, lane);                   // 15 rounds, 2-way ILP
        u64 w = shflx64(v1, 31);                  // reverse of v1
        v0 = (v0 < w) ? v0 : w;                   // bitonic sequence of mins
        #pragma unroll
        for (int j = 16; j > 0; j >>= 1)          // 5-round bitonic merge
            cswap(v0, j, (lane & j) == 0);
    }

    const bool  val = (v0 != PADKEY);
    const float rd  = __uint_as_float((u32)(v0 >> 32));
    const int   ri  = (int)(u32)v0;
    out_idx[o]  = val ? (float)ri : -1.0f;
    out_dist[o] = val ? sqrtf(fmaxf(rd, 1e-12f)) : 0.0f;
}

// ---------------------------------------------------------------------------
extern "C" void kernel_launch(void* const* d_in, const int* in_sizes, int n_in,
                              void* d_out, int out_size)
{
    const float* points     = (const float*)d_in[0];
    const int*   row_splits = (const int*)  d_in[1];
    const float* qpts       = (const float*)d_in[2];
    const int*   q_splits   = (const int*)  d_in[3];

    const int n_qs = in_sizes[3];
    const int B    = in_sizes[1] - 1;
    const int Q    = in_sizes[2] / 3;

    float* out_idx  = (float*)d_out;
    float* out_dist = out_idx + (size_t)Q * FRNQ_LIMIT;

    frnq_prep_kernel<<<B, PREP_T>>>(points, row_splits);

    const int qblocks = (Q + FRNQ_QWARPS - 1) / FRNQ_QWARPS;
    frnq_query_kernel<<<qblocks, FRNQ_QTHREADS>>>(qpts, q_splits, n_qs,
                                                  Q, out_idx, out_dist);
}

// round 14
// speedup vs baseline: 1.3826x; 1.0899x over previous
#include <cuda_runtime.h>
#include <math.h>

// FixedRadiusNeighborQuery — 2-D binned pruning + smem-atomic compaction,
// with Programmatic Dependent Launch overlapping prep and query startup.
//
//   K1 prep (one block per batch, 1024 thr): smem 64x64 histogram ->
//      in-place block exclusive scan -> g_start; smem-cursor scatter of
//      bin-sorted float4{x,y,z,p2} + orig idx. Signals
//      griddepcontrol.launch_dependents when its writes are done.
//   K2 query (PDL secondary): preamble (qpts, q2, bin windows, batch id)
//      runs concurrently with K1's tail; griddepcontrol.wait before the
//      first read of g_start/g_pts4. 1 warp/query; scans bins intersecting
//      [q-0.302,q+0.302]^2 (provable superset of the reference accept set:
//      bin fn monotone, 0.302 >> max accepted |dx| = 0.30017 incl. d2-chain
//      fp error). Hits compacted via per-warp smem atomicAdd; (d2bits,idx)
//      keys bitonic-sorted (10/15/20+5 rounds for cnt<=16/32/64) -> exact
//      (d2 asc, idx asc) top-32. cnt>64 -> noinline fallback rescan.
//
// Numerics identical to the JAX reference:
//   p2 = (x*x + y*y) + z*z ;  dot = fma(qz,pz, fma(qy,py, qx*px))
//   d2 = fma(dot,-2, q2+p2) ; valid = d2 <= 0.09f
//   dist = sqrtf(max(max(d2,0),1e-12))

#define FRNQ_LIMIT 32
#define NX 64
#define NBINS2 (NX * NX)
#define MAXN  65536
#define MAXB  16
#define XMIN  (-6.5f)
#define INVW  (NX / 13.0f)
#define RWIN  0.302f

typedef unsigned long long u64;
typedef unsigned int u32;

__device__ float4 g_pts4[MAXN];
__device__ int    g_pidx[MAXN];
__device__ int    g_start[MAXB * (NBINS2 + 1)];

__device__ __forceinline__ int bin1(float v) {
    int b = (int)floorf((v - XMIN) * INVW);
    return min(max(b, 0), NX - 1);
}

// ---------------- K1: fused count + scan + scatter (1 block per batch) -----
#define PREP_T 1024
#define PREP_V (NBINS2 / PREP_T)   // 4 bins per thread

__global__ __launch_bounds__(PREP_T)
void frnq_prep_kernel(const float* __restrict__ points,
                      const int*   __restrict__ row_splits)
{
    __shared__ int hist[NBINS2];          // hist -> absolute cursor, in place
    __shared__ int wsum[PREP_T / 32];

    const int b    = blockIdx.x;
    const int ps   = row_splits[b];
    const int pe   = row_splits[b + 1];
    const int tid  = threadIdx.x;
    const int lane = tid & 31;
    const int wid  = tid >> 5;
    const int base = tid * PREP_V;

    #pragma unroll
    for (int v = 0; v < PREP_V; ++v) hist[base + v] = 0;
    __syncthreads();

    for (int i = ps + tid; i < pe; i += PREP_T) {
        int bx = bin1(points[3 * i + 0]);
        int by = bin1(points[3 * i + 1]);
        atomicAdd(&hist[by * NX + bx], 1);
    }
    __syncthreads();

    int loc[PREP_V];
    int s = 0;
    #pragma unroll
    for (int v = 0; v < PREP_V; ++v) { loc[v] = s; s += hist[base + v]; }

    int inc = s;
    #pragma unroll
    for (int o = 1; o < 32; o <<= 1) {
        int t = __shfl_up_sync(0xffffffffu, inc, o);
        if (lane >= o) inc += t;
    }
    if (lane == 31) wsum[wid] = inc;
    __syncthreads();
    if (wid == 0) {
        int w  = wsum[lane];
        int wi = w;
        #pragma unroll
        for (int o = 1; o < 32; o <<= 1) {
            int t = __shfl_up_sync(0xffffffffu, wi, o);
            if (lane >= o) wi += t;
        }
        wsum[lane] = wi - w;
    }
    __syncthreads();
    const int excl = inc - s + wsum[wid];

    const int gb = b * (NBINS2 + 1);
    #pragma unroll
    for (int v = 0; v < PREP_V; ++v) {
        int pos = ps + excl + loc[v];
        g_start[gb + base + v] = pos;
        hist[base + v] = pos;
    }
    if (tid == 0) g_start[gb + NBINS2] = pe;
    __syncthreads();

    for (int i = ps + tid; i < pe; i += PREP_T) {
        float x = points[3 * i + 0];
        float y = points[3 * i + 1];
        float z = points[3 * i + 2];
        float p2 = __fadd_rn(__fadd_rn(__fmul_rn(x, x), __fmul_rn(y, y)),
                             __fmul_rn(z, z));
        int bn  = bin1(y) * NX + bin1(x);
        int pos = atomicAdd(&hist[bn], 1);
        g_pts4[pos] = make_float4(x, y, z, p2);
        g_pidx[pos] = i;
    }

    // allow the dependent (query) grid to launch as this CTA's work retires
    asm volatile("griddepcontrol.launch_dependents;");
}

// ---------------- K2: query ----------------
#define FRNQ_QWARPS 8
#define FRNQ_QTHREADS (FRNQ_QWARPS * 32)
#define CAP 64
#define PADKEY 0xFFFFFFFFFFFFFFFFull

__device__ __forceinline__ u64 shflx64(u64 v, int j) {
    return __shfl_xor_sync(0xffffffffu, v, j);
}
__device__ __forceinline__ void cswap(u64& v, int j, bool takeMin) {
    u64 o  = shflx64(v, j);
    u64 mn = (v < o) ? v : o;
    u64 mx = (v < o) ? o : v;
    v = takeMin ? mn : mx;
}
// ascending bitonic sort of N keys in lanes [0,N); other lanes hold PADKEY
template <int N>
__device__ __forceinline__ void sortN(u64& v, int lane) {
    #pragma unroll
    for (int k = 2; k <= N; k <<= 1) {
        #pragma unroll
        for (int j = k >> 1; j > 0; j >>= 1) {
            bool up    = ((lane & k) == 0) || (k == N);
            bool lower = ((lane & j) == 0);
            cswap(v, j, up == lower);
        }
    }
}
__device__ __forceinline__ void sort32x2(u64& a, u64& b, int lane) {
    #pragma unroll
    for (int k = 2; k <= 32; k <<= 1) {
        #pragma unroll
        for (int j = k >> 1; j > 0; j >>= 1) {
            bool up    = ((lane & k) == 0) || (k == 32);
            bool lower = ((lane & j) == 0);
            bool tm    = (up == lower);
            cswap(a, j, tm);
            cswap(b, j, tm);
        }
    }
}

// Fallback: per-lane insert lists + reduce-merge (proven R8 path). Rare.
__device__ __noinline__
void frnq_fallback(int q, int lane, float qx, float qy, float qz, float q2,
                   const int* st, int bxlo, int bxhi, int bylo, int byhi,
                   float* out_idx, float* out_dist)
{
    const float R2  = 0.09f;
    const float INF = __int_as_float(0x7f800000);
    float ld[FRNQ_LIMIT];
    int   li[FRNQ_LIMIT];
    int   n = 0;

    for (int by = bylo; by <= byhi; ++by) {
        const int beg = st[by * NX + bxlo];
        const int end = st[by * NX + bxhi + 1];
        for (int k = beg + lane; k < end; k += 32) {
            float4 p  = g_pts4[k];
            float dot = __fmaf_rn(qz, p.z, __fmaf_rn(qy, p.y, __fmul_rn(qx, p.x)));
            float d2  = __fmaf_rn(dot, -2.0f, __fadd_rn(q2, p.w));
            if (d2 <= R2) {
                d2 = fmaxf(d2, 0.0f);
                int idx = g_pidx[k];
                if (n < FRNQ_LIMIT || d2 < ld[FRNQ_LIMIT - 1]) {
                    int j = (n < FRNQ_LIMIT) ? n : (FRNQ_LIMIT - 1);
                    while (j > 0 && ld[j - 1] > d2) {
                        ld[j] = ld[j - 1]; li[j] = li[j - 1]; --j;
                    }
                    ld[j] = d2; li[j] = idx;
                    if (n < FRNQ_LIMIT) ++n;
                }
            }
        }
    }

    int   pos = 0;
    float hd  = (n > 0) ? ld[0] : INF;
    int   hi2 = (n > 0) ? li[0] : 0x7fffffff;
    float rd  = INF;
    int   ri  = -1;
    for (int r = 0; r < FRNQ_LIMIT; ++r) {
        float bd = hd;
        #pragma unroll
        for (int off = 16; off > 0; off >>= 1)
            bd = fminf(bd, __shfl_xor_sync(0xffffffffu, bd, off));
        if (bd == INF) break;
        unsigned m  = __ballot_sync(0xffffffffu, hd == bd);
        int      wl = __ffs(m) - 1;
        if (__popc(m) > 1) {
            int myi = (hd == bd) ? hi2 : 0x7fffffff;
            int mi  = myi;
            #pragma unroll
            for (int off = 16; off > 0; off >>= 1)
                mi = min(mi, __shfl_xor_sync(0xffffffffu, mi, off));
            m  = __ballot_sync(0xffffffffu, myi == mi);
            wl = __ffs(m) - 1;
        }
        int wi = __shfl_sync(0xffffffffu, hi2, wl);
        if (r == lane) { rd = bd; ri = wi; }
        if (lane == wl) {
            ++pos;
            if (pos < n) { hd = ld[pos]; hi2 = li[pos]; }
            else         { hd = INF;     hi2 = 0x7fffffff; }
        }
    }
    const size_t o   = (size_t)q * FRNQ_LIMIT + lane;
    const bool   val = (rd < 1e29f);
    out_idx[o]  = val ? (float)ri : -1.0f;
    out_dist[o] = val ? sqrtf(fmaxf(rd, 1e-12f)) : 0.0f;
}

__global__ __launch_bounds__(FRNQ_QTHREADS)
void frnq_query_kernel(const float* __restrict__ qpts,
                       const int*   __restrict__ q_splits, int n_qs,
                       int Q,
                       float* __restrict__ out_idx,
                       float* __restrict__ out_dist)
{
    __shared__ u64 buf[FRNQ_QWARPS][CAP];
    __shared__ int wcnt[FRNQ_QWARPS];

    const int lane = threadIdx.x & 31;
    const int warp = threadIdx.x >> 5;
    const int q    = blockIdx.x * FRNQ_QWARPS + warp;
    if (q >= Q) {
        asm volatile("griddepcontrol.wait;");   // still honor the PDL edge
        return;
    }

    const float R2 = 0.09f;

    if (lane == 0) wcnt[warp] = 0;

    // ---- preamble: independent of prep outputs; overlaps prep via PDL ----
    int qb = 0;
    for (int i = 1; i < n_qs; ++i)
        if (q_splits[i] <= q) qb = i;

    const float qx = qpts[3 * q + 0];
    const float qy = qpts[3 * q + 1];
    const float qz = qpts[3 * q + 2];
    const float q2 = __fadd_rn(__fadd_rn(__fmul_rn(qx, qx), __fmul_rn(qy, qy)),
                               __fmul_rn(qz, qz));

    const int bxlo  = bin1(qx - RWIN);
    const int bxhi  = bin1(qx + RWIN);
    const int bylo  = bin1(qy - RWIN);
    const int byhi  = bin1(qy + RWIN);
    const int nrows = byhi - bylo + 1;
    const int* st   = g_start + qb * (NBINS2 + 1);

    // ---- wait for prep's writes (g_start / g_pts4 / g_pidx) ----
    asm volatile("griddepcontrol.wait;");

    // one parallel LDG round for all row ranges, shfl-broadcast later
    int sv = 0;
    if (lane < 2 * nrows)
        sv = st[(bylo + (lane >> 1)) * NX + ((lane & 1) ? (bxhi + 1) : bxlo)];
    __syncwarp();   // wcnt init + sv ready

    // scan loop: NO per-iteration warp sync — hit path takes a smem atomic.
    for (int r = 0; r < nrows; ++r) {
        const int beg = __shfl_sync(0xffffffffu, sv, 2 * r);
        const int end = __shfl_sync(0xffffffffu, sv, 2 * r + 1);
        for (int k = beg + lane; k < end; k += 32) {
            float4 p  = g_pts4[k];
            float dot = __fmaf_rn(qz, p.z, __fmaf_rn(qy, p.y, __fmul_rn(qx, p.x)));
            float d2  = __fmaf_rn(dot, -2.0f, __fadd_rn(q2, p.w));
            if (d2 <= R2) {                        // rare (~5% of evals)
                int off = atomicAdd(&wcnt[warp], 1);
                if (off < CAP) {
                    float d2c = fmaxf(d2, 0.0f);
                    buf[warp][off] = ((u64)__float_as_uint(d2c) << 32) |
                                     (u32)g_pidx[k];
                }
            }
        }
    }
    __syncwarp();
    const int cnt = wcnt[warp];

    const size_t o = (size_t)q * FRNQ_LIMIT + lane;

    if (cnt == 0) {                 // warp-uniform: skip the sort entirely
        out_idx[o]  = -1.0f;
        out_dist[o] = 0.0f;
        return;
    }
    if (cnt > CAP) {                // practically never; correctness anyway
        frnq_fallback(q, lane, qx, qy, qz, q2, st,
                      bxlo, bxhi, bylo, byhi, out_idx, out_dist);
        return;
    }

    u64 v0 = (lane < cnt) ? buf[warp][lane] : PADKEY;

    if (cnt <= 16) {
        sortN<16>(v0, lane);                      // 10 rounds
    } else if (cnt <= 32) {
        sortN<32>(v0, lane);                      // 15 rounds
    } else {
        u64 v1 = (lane + 32 < cnt) ? buf[warp][lane + 32] : PADKEY;
        sort32x2(v0, v1, lane);                   // 15 rounds, 2-way ILP
        u64 w = shflx64(v1, 31);                  // reverse of v1
        v0 = (v0 < w) ? v0 : w;                   // bitonic sequence of mins
        #pragma unroll
        for (int j = 16; j > 0; j >>= 1)          // 5-round bitonic merge
            cswap(v0, j, (lane & j) == 0);
    }

    const bool  val = (v0 != PADKEY);
    const float rd  = __uint_as_float((u32)(v0 >> 32));
    const int   ri  = (int)(u32)v0;
    out_idx[o]  = val ? (float)ri : -1.0f;
    out_dist[o] = val ? sqrtf(fmaxf(rd, 1e-12f)) : 0.0f;
}

// ---------------------------------------------------------------------------
extern "C" void kernel_launch(void* const* d_in, const int* in_sizes, int n_in,
                              void* d_out, int out_size)
{
    const float* points     = (const float*)d_in[0];
    const int*   row_splits = (const int*)  d_in[1];
    const float* qpts       = (const float*)d_in[2];
    const int*   q_splits   = (const int*)  d_in[3];

    const int n_qs = in_sizes[3];
    const int B    = in_sizes[1] - 1;
    const int Q    = in_sizes[2] / 3;

    float* out_idx  = (float*)d_out;
    float* out_dist = out_idx + (size_t)Q * FRNQ_LIMIT;

    frnq_prep_kernel<<<B, PREP_T>>>(points, row_splits);

    const int qblocks = (Q + FRNQ_QWARPS - 1) / FRNQ_QWARPS;

    cudaLaunchConfig_t cfg = {};
    cfg.gridDim  = dim3((unsigned)qblocks, 1, 1);
    cfg.blockDim = dim3(FRNQ_QTHREADS, 1, 1);
    cfg.dynamicSmemBytes = 0;
    cfg.stream = 0;
    cudaLaunchAttribute attr[1];
    attr[0].id = cudaLaunchAttributeProgrammaticStreamSerialization;
    attr[0].val.programmaticStreamSerializationAllowed = 1;
    cfg.attrs = attr;
    cfg.numAttrs = 1;
    cudaLaunchKernelEx(&cfg, frnq_query_kernel,
                       qpts, q_splits, n_qs, Q, out_idx, out_dist);
}